// round 2
// baseline (speedup 1.0000x reference)
#include <cuda_runtime.h>
#include <cstdint>

constexpr int NB    = 256;   // batch
constexpr int BSTR  = 65;    // padded stride for [comp][feat] buffers
constexpr int BUFSZ = 64 * BSTR;

struct SMLayout {
    float    buf[3][BUFSZ];   // multivector buffers, comp-major: buf[i*BSTR + f]
    float    LW[BUFSZ];       // staged linear weights [m][f] (stride BSTR); reused for mlp_w1
    float    WGP[BUFSZ];      // staged gp_w per layer: [f][widx] (stride BSTR)
    unsigned tab[4096];       // packed Cayley table [i][out_j]
    float    FACT[256];       // per (f, class) normalize factors; reused as Y4 partials
    int      qts[64];
    int      clss[80];        // 4 classes x up to 20 members
    int      ncls[4];
    float    scratch[160];    // points (96) -> ysh(64)+hsh(64)
};

__device__ unsigned g_tab[4096];
__device__ int      g_qt[64];
__device__ int      g_cls[80];
__device__ int      g_ncls[4];
__device__ float    g_lwT[4 * 4 * 64 * 64];   // [layer][class][m][f]
__device__ float    g_loss_scratch[NB];

// ---------------------------------------------------------------------------
// Init: build algebra tables + transpose gp_lin_w for coalesced staging.
// Table entry for (i, j_out): second-operand index k (as k*65), packed
// w-class index (qt_i, qt_jout, qt_k), and the Cayley sign.
// ---------------------------------------------------------------------------
__global__ void ch_init(const float* __restrict__ gp_lin_w)
{
    const int t = threadIdx.x;
    if (blockIdx.x == 0) {
        __shared__ int s_mask[64], s_pos[64], s_qt[64];
        if (t == 0) {
            int idx = 0;
            for (int g = 0; g <= 6; ++g)
                for (int m = 0; m < 64; ++m)
                    if (__popc(m) == g) s_mask[idx++] = m;
            for (int i = 0; i < 64; ++i) s_pos[s_mask[i]] = i;
            int nc[4] = {0, 0, 0, 0};
            for (int i = 0; i < 64; ++i) {
                const int q = __popc(s_mask[i]) & 3;
                s_qt[i] = q;
                g_qt[i] = q;
                g_cls[q * 20 + nc[q]] = i;
                nc[q]++;
            }
            for (int c = 0; c < 4; ++c) g_ncls[c] = nc[c];
        }
        __syncthreads();
        for (int e = t; e < 4096; e += blockDim.x) {
            const int i = e >> 6, j = e & 63;        // j = OUTPUT component index
            const int mi = s_mask[i];
            const int mk = mi ^ s_mask[j];           // mask of second operand
            const int k  = s_pos[mk];                // second-operand index
            int sgn = 0, tt = mi >> 1;
            while (tt) { sgn += __popc(tt & mk); tt >>= 1; }
            const int widx = (s_qt[i] * 4 + s_qt[j]) * 4 + s_qt[k]; // (qti, qt_out, qt_2nd)
            g_tab[e] = (unsigned)(k * BSTR)
                     | ((unsigned)widx << 16)
                     | ((unsigned)(sgn & 1) << 31);
        }
    } else {
        const int base = (blockIdx.x - 1) * 1024;
        #pragma unroll
        for (int r = 0; r < 4; ++r) {
            const int e = base + r * 256 + t;   // [l][c][m][f]
            const int f = e & 63, m = (e >> 6) & 63, c = (e >> 12) & 3, l = e >> 14;
            g_lwT[e] = gp_lin_w[((l * 64 + f) * 64 + m) * 4 + c];
        }
    }
}

// ---------------------------------------------------------------------------
// Main: one block per batch element.
// ---------------------------------------------------------------------------
__global__ void __launch_bounds__(256, 2)
ch_main(const float* __restrict__ points,
        const float* __restrict__ products,
        const float* __restrict__ lin_w,
        const float* __restrict__ lin_b,
        const float* __restrict__ gp_a,
        const float* __restrict__ gp_w,
        const float* __restrict__ mlp_w1,
        const float* __restrict__ mlp_b1,
        const float* __restrict__ mlp_w2,
        const float* __restrict__ mlp_b2,
        float* __restrict__ lossp)
{
    extern __shared__ unsigned char smraw[];
    SMLayout* s = reinterpret_cast<SMLayout*>(smraw);

    const int t = threadIdx.x;
    const int b = blockIdx.x;

    // ---- stage constants ----
    for (int e = t; e < 4096; e += 256) s->tab[e] = g_tab[e];
    if (t < 64) s->qts[t] = g_qt[t];
    if (t < 80) s->clss[t] = g_cls[t];
    if (t < 4)  s->ncls[t] = g_ncls[t];
    if (t < 96) s->scratch[t] = points[b * 96 + t];

    // ---- zero x buffer ----
    {
        float* A0 = s->buf[0];
        for (int e = t; e < BUFSZ; e += 256) A0[e] = 0.f;
    }
    __syncthreads();

    // ---- initial qt_linear (grade-1 inputs only -> class 1 weights; bias on comp 0)
    {
        float* A0 = s->buf[0];
        if (t < 64) A0[t] = lin_b[t];                  // comp 0
        for (int o = t; o < 384; o += 256) {
            const int f = o / 6, d = o % 6;
            float acc = 0.f;
            #pragma unroll
            for (int m = 0; m < 16; ++m)
                acc = fmaf(s->scratch[m * 6 + d], __ldg(&lin_w[(f * 16 + m) * 4 + 1]), acc);
            A0[(1 + d) * BSTR + f] = acc;
        }
    }
    __syncthreads();

    // ---- 4 GP layers ----
    int oa = 0, oc = 2;
    for (int l = 0; l < 4; ++l) {
        float* A = s->buf[oa];
        float* B = s->buf[1];
        float* C = s->buf[oc];

        // qt_linear: B[i][f] = sum_m A[i][m] * gp_lin_w[l,f,m,qt(i)] (class-staged)
        {
            const float* lwTl = g_lwT + l * 4 * 4096;
            const int f64 = t & 63, ig = t >> 6;
            for (int c = 0; c < 4; ++c) {
                __syncthreads();
                const float* src = lwTl + c * 4096;
                for (int e = t; e < 4096; e += 256)
                    s->LW[(e >> 6) * BSTR + (e & 63)] = src[e];   // [m][f]
                __syncthreads();
                const int nc = s->ncls[c];
                const int* cl = s->clss + c * 20;
                for (int idx = ig; idx < nc; idx += 8) {
                    const int i0 = cl[idx];
                    const bool has1 = (idx + 4) < nc;
                    const int i1 = has1 ? cl[idx + 4] : i0;
                    const float* Ar0 = A + i0 * BSTR;
                    const float* Ar1 = A + i1 * BSTR;
                    float a0 = 0.f, a1 = 0.f;
                    #pragma unroll
                    for (int m = 0; m < 64; ++m) {
                        const float w = s->LW[m * BSTR + f64];
                        a0 = fmaf(Ar0[m], w, a0);
                        a1 = fmaf(Ar1[m], w, a1);
                    }
                    B[i0 * BSTR + f64] = a0;
                    if (has1) B[i1 * BSTR + f64] = a1;
                }
            }
        }
        __syncthreads();

        // normalize B per (feature, qt-class)
        {
            const int ff = t & 63, c = t >> 6;
            const int nc = s->ncls[c];
            const int* cl = s->clss + c * 20;
            float sum = 0.f;
            for (int idx = 0; idx < nc; ++idx) {
                const float v = B[cl[idx] * BSTR + ff];
                sum = fmaf(v, v, sum);
            }
            const float nrm = sqrtf(fmaxf(sum, 1e-12f));
            const float av  = gp_a[(l * 64 + ff) * 4 + c];
            const float sig = 1.f / (1.f + expf(-av));
            s->FACT[ff * 4 + c] = 1.f / (fmaf(sig, nrm - 1.f, 1.f) + 1e-6f);
        }
        __syncthreads();
        for (int r = 0; r < 16; ++r) {
            const int e = r * 256 + t;
            const int i = e >> 6, ff = e & 63;
            B[i * BSTR + ff] *= s->FACT[ff * 4 + s->qts[i]];
        }
        // stage gp_w for this layer: WGP[f][widx]
        {
            const float* gw = gp_w + l * 4096;
            for (int e = t; e < 4096; e += 256)
                s->WGP[(e >> 6) * BSTR + (e & 63)] = gw[e];
        }
        __syncthreads();

        // geometric product: C[j][f] = sum_i sign * w[f,qti,qtj,qtk] * A[i][f] * B[k][f]
        {
            const int ff = t >> 2, jg = t & 3;
            const float* Af = A + ff;
            const float* Bf = B + ff;
            const float* Wf = s->WGP + ff * BSTR;
            const uint4* trow = reinterpret_cast<const uint4*>(s->tab) + jg * 4;
            float acc[16];
            #pragma unroll
            for (int q = 0; q < 16; ++q) acc[q] = 0.f;
            for (int i = 0; i < 64; ++i) {
                const float xi = Af[i * BSTR];
                const uint4 v0 = trow[i * 16 + 0];
                const uint4 v1 = trow[i * 16 + 1];
                const uint4 v2 = trow[i * 16 + 2];
                const uint4 v3 = trow[i * 16 + 3];
                const unsigned es[16] = { v0.x, v0.y, v0.z, v0.w,
                                          v1.x, v1.y, v1.z, v1.w,
                                          v2.x, v2.y, v2.z, v2.w,
                                          v3.x, v3.y, v3.z, v3.w };
                #pragma unroll
                for (int q = 0; q < 16; ++q) {
                    const unsigned e = es[q];
                    float p = xi * Bf[e & 0x1FFFu];
                    p = __int_as_float(__float_as_int(p) ^ (int)(e & 0x80000000u));
                    acc[q] = fmaf(Wf[(e >> 16) & 63u], p, acc[q]);
                }
            }
            #pragma unroll
            for (int q = 0; q < 16; ++q)
                C[(jg * 16 + q) * BSTR + ff] = acc[q];
        }
        __syncthreads();

        const int tmp = oa; oa = oc; oc = tmp;   // new x = C
    }

    // ---- final: y = ||x||, h = silu(y@W1^T + b1), pred = h@w2 + b2, loss ----
    {
        float* X  = s->buf[oa];
        float* Y4 = s->FACT;   // reuse: 4 partials x 64 features
        {
            const int ff = t & 63, part = t >> 6;
            float sum = 0.f;
            #pragma unroll
            for (int r = 0; r < 16; ++r) {
                const float v = X[(part * 16 + r) * BSTR + ff];
                sum = fmaf(v, v, sum);
            }
            Y4[part * 64 + ff] = sum;
        }
        __syncthreads();
        float* ysh = s->scratch;        // 64
        float* hsh = s->scratch + 64;   // 64
        if (t < 64) ysh[t] = sqrtf(Y4[t] + Y4[64 + t] + Y4[128 + t] + Y4[192 + t]);
        // stage mlp_w1 as [f][n] (stride BSTR)
        for (int e = t; e < 4096; e += 256) {
            const int n = e >> 6, f = e & 63;
            s->LW[f * BSTR + n] = mlp_w1[e];
        }
        __syncthreads();
        if (t < 64) {
            float a = mlp_b1[t];
            #pragma unroll
            for (int f = 0; f < 64; ++f)
                a = fmaf(ysh[f], s->LW[f * BSTR + t], a);
            const float sig = 1.f / (1.f + expf(-a));
            hsh[t] = a * sig * __ldg(&mlp_w2[t]);   // fold in w2
        }
        __syncthreads();
        if (t == 0) {
            float p = mlp_b2[0];
            for (int n = 0; n < 64; ++n) p += hsh[n];
            const float d = p - products[b];
            lossp[b] = d * d;
        }
    }
}

// ---------------------------------------------------------------------------
// Mean reduce (deterministic tree)
// ---------------------------------------------------------------------------
__global__ void ch_reduce(const float* __restrict__ lossp, float* __restrict__ out)
{
    __shared__ float sred[NB];
    const int t = threadIdx.x;
    sred[t] = lossp[t];
    __syncthreads();
    for (int sft = NB / 2; sft > 0; sft >>= 1) {
        if (t < sft) sred[t] += sred[t + sft];
        __syncthreads();
    }
    if (t == 0) out[0] = sred[0] * (1.0f / (float)NB);
}

extern "C" void kernel_launch(void* const* d_in, const int* in_sizes, int n_in,
                              void* d_out, int out_size)
{
    const float* points   = (const float*)d_in[0];
    const float* products = (const float*)d_in[1];
    const float* lin_w    = (const float*)d_in[2];
    const float* lin_b    = (const float*)d_in[3];
    const float* gp_lin_w = (const float*)d_in[4];
    const float* gp_a     = (const float*)d_in[5];
    const float* gp_w     = (const float*)d_in[6];
    const float* mlp_w1   = (const float*)d_in[7];
    const float* mlp_b1   = (const float*)d_in[8];
    const float* mlp_w2   = (const float*)d_in[9];
    const float* mlp_b2   = (const float*)d_in[10];
    float* out = (float*)d_out;

    static bool attr_set = false;
    if (!attr_set) {
        cudaFuncSetAttribute(ch_main, cudaFuncAttributeMaxDynamicSharedMemorySize,
                             (int)sizeof(SMLayout));
        attr_set = true;
    }

    ch_init<<<65, 256>>>(gp_lin_w);

    float* lossp;
    bool write_mean = true;
    if (out_size >= NB + 1) {
        lossp = out + 1;                 // layout: [mean, loss[256]]
    } else if (out_size == NB) {
        lossp = out;                     // loss only, no mean slot
        write_mean = false;
    } else {
        void* p = nullptr;
        cudaGetSymbolAddress(&p, g_loss_scratch);
        lossp = (float*)p;               // mean only
    }

    ch_main<<<NB, 256, sizeof(SMLayout)>>>(points, products, lin_w, lin_b,
                                           gp_a, gp_w, mlp_w1, mlp_b1,
                                           mlp_w2, mlp_b2, lossp);
    if (write_mean)
        ch_reduce<<<1, NB>>>(lossp, out);
}